// round 11
// baseline (speedup 1.0000x reference)
#include <cuda_runtime.h>
#include <cstdint>

#define B_    256
#define T_    1000
#define F_    64
#define H1_   256
#define H2_   128
#define NCLS_ 5
#define DMLP_ 128

#define GCOL  16      // column groups (hidden-unit split)
#define GB    8       // batch groups
#define BC    32      // batch rows per batch group (256/8)
#define U1    16      // layer-1 hidden units per column group (256/16)
#define U2    8       // layer-2 hidden units per column group (128/16)
#define NTHR  256

// ---- global exchange state (static device arrays; no allocation) ----
__device__ float g_h1buf[2][B_][H1_];   // slot t&1 holds h1(t)
__device__ float g_h2buf[2][B_][H2_];   // slot t&1 holds h2(t-1)
__device__ int   g_cnt[GB];             // monotonic arrival counter per batch group

// ---- SMEM layout (dynamic, ~184.4 KB) ----
struct SmemLayout {
    float Wh1[H1_][U1 * 4];   // Whh1 slice, [k][j*4+g]          64 KB
    float Wx1[F_][U1 * 4];    // Wih1 slice                       16 KB
    float W2a[H1_][U2 * 4];   // Wih2 slice (input = h1)          32 KB
    float W2b[H2_][U2 * 4];   // Whh2 slice                       16 KB
    float h1s[BC][H1_];       // staged h1(t-1)                   32 KB
    float h2s[BC][H2_];       // staged h2(t-2)                   16 KB
    float xs[BC][F_];         // staged x_t                        8 KB
    float bias1[U1 * 4];
    float bias2[U2 * 4];
};
#define SMEM_BYTES (sizeof(SmemLayout))

// ---- packed fp32x2 helpers (sm_103a dual-rate fp32 path) ----
__device__ __forceinline__ unsigned long long pack2(float a, float b) {
    unsigned long long r;
    asm("mov.b64 %0, {%1, %2};" : "=l"(r) : "f"(a), "f"(b));
    return r;
}
__device__ __forceinline__ float2 unpack2(unsigned long long v) {
    float2 r;
    asm("mov.b64 {%0, %1}, %2;" : "=f"(r.x), "=f"(r.y) : "l"(v));
    return r;
}
#define FMA2(acc, a, b) \
    asm("fma.rn.f32x2 %0, %1, %2, %0;" : "+l"(acc) : "l"(a), "l"(b))

__device__ __forceinline__ float sigf(float v) {
    return 1.0f / (1.0f + __expf(-v));
}
__device__ __forceinline__ float tanh_f(float v) {
    v = fminf(fmaxf(v, -15.0f), 15.0f);   // keep __expf finite
    float e = __expf(-2.0f * v);
    return (1.0f - e) / (1.0f + e);
}

// ---- init: zero initial state + counters (runs every graph replay) ----
__global__ void lstm_init_kernel() {
    int i = blockIdx.x * blockDim.x + threadIdx.x;
    int stride = gridDim.x * blockDim.x;
    if (i < GB) g_cnt[i] = 0;
    for (int j = i; j < B_ * H1_; j += stride) ((float*)g_h1buf)[j] = 0.0f;  // slot 0
    for (int j = i; j < B_ * H2_; j += stride) ((float*)g_h2buf)[j] = 0.0f;  // slot 0 (hygiene)
}

// ---- persistent two-layer LSTM ----
extern "C" __global__ void __launch_bounds__(NTHR, 1)
lstm_persistent(const float* __restrict__ x,
                const float* __restrict__ Wih1, const float* __restrict__ Whh1,
                const float* __restrict__ bih1, const float* __restrict__ bhh1,
                const float* __restrict__ Wih2, const float* __restrict__ Whh2,
                const float* __restrict__ bih2, const float* __restrict__ bhh2)
{
    extern __shared__ float smem_raw[];
    SmemLayout* S = (SmemLayout*)smem_raw;

    const int tid = threadIdx.x;
    const int cg  = blockIdx.x & (GCOL - 1);   // column group
    const int bg  = blockIdx.x >> 4;           // batch group
    const int B0  = bg * BC;
    const int u0  = cg * U1;                   // layer-1 unit base
    const int v0  = cg * U2;                   // layer-2 unit base

    // ---- one-time weight slice load (transposed into [k][unit][gate]) ----
    for (int idx = tid; idx < H1_ * U1 * 4; idx += NTHR) {
        int k = idx >> 6, rem = idx & 63, j = rem >> 2, g = rem & 3;
        S->Wh1[k][rem] = Whh1[(g * H1_ + u0 + j) * H1_ + k];
    }
    for (int idx = tid; idx < F_ * U1 * 4; idx += NTHR) {
        int f = idx >> 6, rem = idx & 63, j = rem >> 2, g = rem & 3;
        S->Wx1[f][rem] = Wih1[(g * H1_ + u0 + j) * F_ + f];
    }
    for (int idx = tid; idx < H1_ * U2 * 4; idx += NTHR) {
        int k = idx >> 5, rem = idx & 31, j = rem >> 2, g = rem & 3;
        S->W2a[k][rem] = Wih2[(g * H2_ + v0 + j) * H1_ + k];
    }
    for (int idx = tid; idx < H2_ * U2 * 4; idx += NTHR) {
        int k = idx >> 5, rem = idx & 31, j = rem >> 2, g = rem & 3;
        S->W2b[k][rem] = Whh2[(g * H2_ + v0 + j) * H2_ + k];
    }
    if (tid < U1 * 4) {
        int j = tid >> 2, g = tid & 3;
        S->bias1[tid] = bih1[g * H1_ + u0 + j] + bhh1[g * H1_ + u0 + j];
    }
    if (tid < U2 * 4) {
        int j = tid >> 2, g = tid & 3;
        S->bias2[tid] = bih2[g * H2_ + v0 + j] + bhh2[g * H2_ + v0 + j];
    }
    __syncthreads();

    const int r  = tid >> 3;     // batch row within group (0..31)
    const int tc = tid & 7;      // column-thread (0..7)
    float c1a = 0.0f, c1b = 0.0f, c2 = 0.0f;   // cell states, register-resident

    // iteration t: layer-1 step t (t<=T), layer-2 step t-1 (t>=2)
    for (int t = 1; t <= T_ + 1; ++t) {
        // ---- wait for all 16 column CTAs to have published step t-1 ----
        if (t > 1) {
            const int target = GCOL * (t - 1);
            if (tid == 0) {
                int v;
                do {
                    asm volatile("ld.acquire.gpu.u32 %0, [%1];"
                                 : "=r"(v) : "l"(&g_cnt[bg]) : "memory");
                } while (v < target);
                __threadfence();
            }
            __syncthreads();
        }
        const int rslot = (t - 1) & 1;

        // ---- stage h1(t-1), h2(t-2), x_t into SMEM ----
        {
            const float4* s1 = (const float4*)&g_h1buf[rslot][B0][0];
            float4* d1 = (float4*)&S->h1s[0][0];
            for (int i = tid; i < BC * H1_ / 4; i += NTHR) d1[i] = s1[i];
            const float4* s2 = (const float4*)&g_h2buf[rslot][B0][0];
            float4* d2 = (float4*)&S->h2s[0][0];
            for (int i = tid; i < BC * H2_ / 4; i += NTHR) d2[i] = s2[i];
            if (t <= T_) {
                float4* dx = (float4*)&S->xs[0][0];
                for (int i = tid; i < BC * F_ / 4; i += NTHR) {
                    int row = i >> 4, col = i & 15;
                    const float4* sx = (const float4*)(x + (size_t)(B0 + row) * T_ * F_
                                                         + (size_t)(t - 1) * F_);
                    dx[i] = sx[col];
                }
            }
        }
        __syncthreads();

        // ---- layer 1: gates for 2 units (j0 = 2*tc, j0+1), 1 batch row ----
        if (t <= T_) {
            const int base = 2 * tc;
            const float* brow = &S->bias1[base * 4];
            unsigned long long a0 = pack2(brow[0], brow[1]);
            unsigned long long a1 = pack2(brow[2], brow[3]);
            unsigned long long a2 = pack2(brow[4], brow[5]);
            unsigned long long a3 = pack2(brow[6], brow[7]);

            const ulonglong2* Wp = (const ulonglong2*)&S->Wh1[0][0];
            const float* hrow = S->h1s[r];
            #pragma unroll 4
            for (int k = 0; k < H1_; ++k) {
                float hv = hrow[k];
                unsigned long long hv2 = pack2(hv, hv);
                ulonglong2 wA = Wp[k * 16 + base];
                ulonglong2 wB = Wp[k * 16 + base + 1];
                FMA2(a0, hv2, wA.x);  FMA2(a1, hv2, wA.y);
                FMA2(a2, hv2, wB.x);  FMA2(a3, hv2, wB.y);
            }
            const ulonglong2* Wxp = (const ulonglong2*)&S->Wx1[0][0];
            const float* xrow = S->xs[r];
            #pragma unroll 4
            for (int f = 0; f < F_; ++f) {
                float xv = xrow[f];
                unsigned long long xv2 = pack2(xv, xv);
                ulonglong2 wA = Wxp[f * 16 + base];
                ulonglong2 wB = Wxp[f * 16 + base + 1];
                FMA2(a0, xv2, wA.x);  FMA2(a1, xv2, wA.y);
                FMA2(a2, xv2, wB.x);  FMA2(a3, xv2, wB.y);
            }

            float2 if0 = unpack2(a0), go0 = unpack2(a1);
            float2 if1 = unpack2(a2), go1 = unpack2(a3);
            float i0 = sigf(if0.x), f0 = sigf(if0.y), g0 = tanh_f(go0.x), o0 = sigf(go0.y);
            c1a = f0 * c1a + i0 * g0;
            float h0 = o0 * tanh_f(c1a);
            float i1 = sigf(if1.x), f1 = sigf(if1.y), g1 = tanh_f(go1.x), o1 = sigf(go1.y);
            c1b = f1 * c1b + i1 * g1;
            float h1v = o1 * tanh_f(c1b);
            *(float2*)&g_h1buf[t & 1][B0 + r][u0 + base] = make_float2(h0, h1v);
        }

        // ---- layer 2 (one step behind): unit v0+tc, 1 batch row ----
        if (t >= 2) {
            const float* brow2 = &S->bias2[tc * 4];
            unsigned long long b0p = pack2(brow2[0], brow2[1]);
            unsigned long long b1p = pack2(brow2[2], brow2[3]);

            const ulonglong2* Wap = (const ulonglong2*)&S->W2a[0][0];
            const float* hrow = S->h1s[r];            // h1(t-1) — input to layer-2 step t-1
            #pragma unroll 4
            for (int k = 0; k < H1_; ++k) {
                float hv = hrow[k];
                unsigned long long hv2 = pack2(hv, hv);
                ulonglong2 w = Wap[k * 8 + tc];
                FMA2(b0p, hv2, w.x);  FMA2(b1p, hv2, w.y);
            }
            const ulonglong2* Wbp = (const ulonglong2*)&S->W2b[0][0];
            const float* h2row = S->h2s[r];           // h2(t-2)
            #pragma unroll 4
            for (int k = 0; k < H2_; ++k) {
                float hv = h2row[k];
                unsigned long long hv2 = pack2(hv, hv);
                ulonglong2 w = Wbp[k * 8 + tc];
                FMA2(b0p, hv2, w.x);  FMA2(b1p, hv2, w.y);
            }
            float2 if2 = unpack2(b0p), go2 = unpack2(b1p);
            float i2 = sigf(if2.x), f2 = sigf(if2.y), g2 = tanh_f(go2.x), o2 = sigf(go2.y);
            c2 = f2 * c2 + i2 * g2;
            g_h2buf[t & 1][B0 + r][v0 + tc] = o2 * tanh_f(c2);
        } else {
            g_h2buf[1][B0 + r][v0 + tc] = 0.0f;       // h2(0) = 0 published at t=1
        }

        // ---- publish: all writes done -> bump counter (release) ----
        __syncthreads();
        if (tid == 0) {
            __threadfence();
            atomicAdd(&g_cnt[bg], 1);
        }
    }
}

// ---- MLP head: out = relu(hT2 @ W1^T + b1) @ W2^T + b2 ----
__global__ void classifier_kernel(const float* __restrict__ W1, const float* __restrict__ b1,
                                  const float* __restrict__ W2, const float* __restrict__ b2,
                                  float* __restrict__ out)
{
    __shared__ float hrow[H2_];
    __shared__ float z[DMLP_];
    const int row = blockIdx.x;
    const int tid = threadIdx.x;   // 128

    hrow[tid] = g_h2buf[(T_ + 1) & 1][row][tid];   // final h2 lives in slot 1
    __syncthreads();

    float acc = b1[tid];
    #pragma unroll 8
    for (int k = 0; k < H2_; ++k) acc += hrow[k] * W1[tid * H2_ + k];
    z[tid] = fmaxf(acc, 0.0f);
    __syncthreads();

    if (tid < NCLS_) {
        float o = b2[tid];
        #pragma unroll 8
        for (int j = 0; j < DMLP_; ++j) o += z[j] * W2[tid * DMLP_ + j];
        out[row * NCLS_ + tid] = o;
    }
}

extern "C" void kernel_launch(void* const* d_in, const int* in_sizes, int n_in,
                              void* d_out, int out_size)
{
    (void)in_sizes; (void)n_in; (void)out_size;
    const float* x    = (const float*)d_in[0];
    const float* Wih1 = (const float*)d_in[1];
    const float* Whh1 = (const float*)d_in[2];
    const float* bih1 = (const float*)d_in[3];
    const float* bhh1 = (const float*)d_in[4];
    const float* Wih2 = (const float*)d_in[5];
    const float* Whh2 = (const float*)d_in[6];
    const float* bih2 = (const float*)d_in[7];
    const float* bhh2 = (const float*)d_in[8];
    const float* W1   = (const float*)d_in[9];
    const float* b1   = (const float*)d_in[10];
    const float* W2   = (const float*)d_in[11];
    const float* b2   = (const float*)d_in[12];
    float* out = (float*)d_out;

    cudaFuncSetAttribute(lstm_persistent,
                         cudaFuncAttributeMaxDynamicSharedMemorySize, (int)SMEM_BYTES);

    lstm_init_kernel<<<256, 256>>>();
    lstm_persistent<<<GB * GCOL, NTHR, SMEM_BYTES>>>(
        x, Wih1, Whh1, bih1, bhh1, Wih2, Whh2, bih2, bhh2);
    classifier_kernel<<<B_, DMLP_>>>(W1, b1, W2, b2, out);
}

// round 12
// speedup vs baseline: 1.0013x; 1.0013x over previous
#include <cuda_runtime.h>
#include <cstdint>

#define B_    256
#define T_    1000
#define F_    64
#define H1_   256
#define H2_   128
#define NCLS_ 5
#define DMLP_ 128

#define GCOL  16      // column groups (hidden-unit split)
#define GB    8       // batch groups
#define BC    32      // batch rows per batch group (256/8)
#define U1    16      // layer-1 hidden units per column group (256/16)
#define U2    8       // layer-2 hidden units per column group (128/16)
#define NTHR  256

// ---- global exchange state (static device arrays; no allocation) ----
__device__ float g_h1buf[2][B_][H1_];   // slot t&1 holds h1(t)
__device__ float g_h2buf[2][B_][H2_];   // slot t&1 holds h2(t-1)
__device__ int   g_cnt[GB];             // monotonic arrival counter per batch group

// ---- SMEM layout (dynamic, ~184.4 KB) ----
struct SmemLayout {
    float Wh1[H1_][U1 * 4];   // Whh1 slice, [k][j*4+g]          64 KB
    float Wx1[F_][U1 * 4];    // Wih1 slice                       16 KB
    float W2a[H1_][U2 * 4];   // Wih2 slice (input = h1)          32 KB
    float W2b[H2_][U2 * 4];   // Whh2 slice                       16 KB
    float h1s[BC][H1_];       // staged h1(t-1)                   32 KB
    float h2s[BC][H2_];       // staged h2(t-2)                   16 KB
    float xs[BC][F_];         // staged x_t                        8 KB
    float bias1[U1 * 4];
    float bias2[U2 * 4];
};
#define SMEM_BYTES (sizeof(SmemLayout))

// ---- packed fp32x2 helpers (sm_103a dual-rate fp32 path) ----
__device__ __forceinline__ unsigned long long pack2(float a, float b) {
    unsigned long long r;
    asm("mov.b64 %0, {%1, %2};" : "=l"(r) : "f"(a), "f"(b));
    return r;
}
__device__ __forceinline__ float2 unpack2(unsigned long long v) {
    float2 r;
    asm("mov.b64 {%0, %1}, %2;" : "=f"(r.x), "=f"(r.y) : "l"(v));
    return r;
}
#define FMA2(acc, a, b) \
    asm("fma.rn.f32x2 %0, %1, %2, %0;" : "+l"(acc) : "l"(a), "l"(b))

__device__ __forceinline__ float sigf(float v) {
    return 1.0f / (1.0f + __expf(-v));
}
__device__ __forceinline__ float tanh_f(float v) {
    v = fminf(fmaxf(v, -15.0f), 15.0f);   // keep __expf finite
    float e = __expf(-2.0f * v);
    return (1.0f - e) / (1.0f + e);
}

// ---- init: zero initial state + counters (runs every graph replay) ----
__global__ void lstm_init_kernel() {
    int i = blockIdx.x * blockDim.x + threadIdx.x;
    int stride = gridDim.x * blockDim.x;
    if (i < GB) g_cnt[i] = 0;
    for (int j = i; j < B_ * H1_; j += stride) ((float*)g_h1buf)[j] = 0.0f;  // slot 0
    for (int j = i; j < B_ * H2_; j += stride) ((float*)g_h2buf)[j] = 0.0f;  // slot 0 (hygiene)
}

// ---- persistent two-layer LSTM ----
extern "C" __global__ void __launch_bounds__(NTHR, 1)
lstm_persistent(const float* __restrict__ x,
                const float* __restrict__ Wih1, const float* __restrict__ Whh1,
                const float* __restrict__ bih1, const float* __restrict__ bhh1,
                const float* __restrict__ Wih2, const float* __restrict__ Whh2,
                const float* __restrict__ bih2, const float* __restrict__ bhh2)
{
    extern __shared__ float smem_raw[];
    SmemLayout* S = (SmemLayout*)smem_raw;

    const int tid = threadIdx.x;
    const int cg  = blockIdx.x & (GCOL - 1);   // column group
    const int bg  = blockIdx.x >> 4;           // batch group
    const int B0  = bg * BC;
    const int u0  = cg * U1;                   // layer-1 unit base
    const int v0  = cg * U2;                   // layer-2 unit base

    // ---- one-time weight slice load (transposed into [k][unit][gate]) ----
    for (int idx = tid; idx < H1_ * U1 * 4; idx += NTHR) {
        int k = idx >> 6, rem = idx & 63, j = rem >> 2, g = rem & 3;
        S->Wh1[k][rem] = Whh1[(g * H1_ + u0 + j) * H1_ + k];
    }
    for (int idx = tid; idx < F_ * U1 * 4; idx += NTHR) {
        int f = idx >> 6, rem = idx & 63, j = rem >> 2, g = rem & 3;
        S->Wx1[f][rem] = Wih1[(g * H1_ + u0 + j) * F_ + f];
    }
    for (int idx = tid; idx < H1_ * U2 * 4; idx += NTHR) {
        int k = idx >> 5, rem = idx & 31, j = rem >> 2, g = rem & 3;
        S->W2a[k][rem] = Wih2[(g * H2_ + v0 + j) * H1_ + k];
    }
    for (int idx = tid; idx < H2_ * U2 * 4; idx += NTHR) {
        int k = idx >> 5, rem = idx & 31, j = rem >> 2, g = rem & 3;
        S->W2b[k][rem] = Whh2[(g * H2_ + v0 + j) * H2_ + k];
    }
    if (tid < U1 * 4) {
        int j = tid >> 2, g = tid & 3;
        S->bias1[tid] = bih1[g * H1_ + u0 + j] + bhh1[g * H1_ + u0 + j];
    }
    if (tid < U2 * 4) {
        int j = tid >> 2, g = tid & 3;
        S->bias2[tid] = bih2[g * H2_ + v0 + j] + bhh2[g * H2_ + v0 + j];
    }
    __syncthreads();

    const int r  = tid >> 3;     // batch row within group (0..31)
    const int tc = tid & 7;      // column-thread (0..7)
    float c1a = 0.0f, c1b = 0.0f, c2 = 0.0f;   // cell states, register-resident

    // iteration t: layer-1 step t (t<=T), layer-2 step t-1 (t>=2)
    for (int t = 1; t <= T_ + 1; ++t) {
        // ---- wait for all 16 column CTAs to have published step t-1 ----
        if (t > 1) {
            const int target = GCOL * (t - 1);
            if (tid == 0) {
                int v;
                do {
                    asm volatile("ld.acquire.gpu.u32 %0, [%1];"
                                 : "=r"(v) : "l"(&g_cnt[bg]) : "memory");
                } while (v < target);
                __threadfence();
            }
            __syncthreads();
        }
        const int rslot = (t - 1) & 1;

        // ---- stage h1(t-1), h2(t-2), x_t into SMEM ----
        {
            const float4* s1 = (const float4*)&g_h1buf[rslot][B0][0];
            float4* d1 = (float4*)&S->h1s[0][0];
            for (int i = tid; i < BC * H1_ / 4; i += NTHR) d1[i] = s1[i];
            const float4* s2 = (const float4*)&g_h2buf[rslot][B0][0];
            float4* d2 = (float4*)&S->h2s[0][0];
            for (int i = tid; i < BC * H2_ / 4; i += NTHR) d2[i] = s2[i];
            if (t <= T_) {
                float4* dx = (float4*)&S->xs[0][0];
                for (int i = tid; i < BC * F_ / 4; i += NTHR) {
                    int row = i >> 4, col = i & 15;
                    const float4* sx = (const float4*)(x + (size_t)(B0 + row) * T_ * F_
                                                         + (size_t)(t - 1) * F_);
                    dx[i] = sx[col];
                }
            }
        }
        __syncthreads();

        // ---- layer 1: gates for 2 units (j0 = 2*tc, j0+1), 1 batch row ----
        if (t <= T_) {
            const int base = 2 * tc;
            const float* brow = &S->bias1[base * 4];
            unsigned long long a0 = pack2(brow[0], brow[1]);
            unsigned long long a1 = pack2(brow[2], brow[3]);
            unsigned long long a2 = pack2(brow[4], brow[5]);
            unsigned long long a3 = pack2(brow[6], brow[7]);

            const ulonglong2* Wp = (const ulonglong2*)&S->Wh1[0][0];
            const float* hrow = S->h1s[r];
            #pragma unroll 4
            for (int k = 0; k < H1_; ++k) {
                float hv = hrow[k];
                unsigned long long hv2 = pack2(hv, hv);
                ulonglong2 wA = Wp[k * 16 + base];
                ulonglong2 wB = Wp[k * 16 + base + 1];
                FMA2(a0, hv2, wA.x);  FMA2(a1, hv2, wA.y);
                FMA2(a2, hv2, wB.x);  FMA2(a3, hv2, wB.y);
            }
            const ulonglong2* Wxp = (const ulonglong2*)&S->Wx1[0][0];
            const float* xrow = S->xs[r];
            #pragma unroll 4
            for (int f = 0; f < F_; ++f) {
                float xv = xrow[f];
                unsigned long long xv2 = pack2(xv, xv);
                ulonglong2 wA = Wxp[f * 16 + base];
                ulonglong2 wB = Wxp[f * 16 + base + 1];
                FMA2(a0, xv2, wA.x);  FMA2(a1, xv2, wA.y);
                FMA2(a2, xv2, wB.x);  FMA2(a3, xv2, wB.y);
            }

            float2 if0 = unpack2(a0), go0 = unpack2(a1);
            float2 if1 = unpack2(a2), go1 = unpack2(a3);
            float i0 = sigf(if0.x), f0 = sigf(if0.y), g0 = tanh_f(go0.x), o0 = sigf(go0.y);
            c1a = f0 * c1a + i0 * g0;
            float h0 = o0 * tanh_f(c1a);
            float i1 = sigf(if1.x), f1 = sigf(if1.y), g1 = tanh_f(go1.x), o1 = sigf(go1.y);
            c1b = f1 * c1b + i1 * g1;
            float h1v = o1 * tanh_f(c1b);
            *(float2*)&g_h1buf[t & 1][B0 + r][u0 + base] = make_float2(h0, h1v);
        }

        // ---- layer 2 (one step behind): unit v0+tc, 1 batch row ----
        if (t >= 2) {
            const float* brow2 = &S->bias2[tc * 4];
            unsigned long long b0p = pack2(brow2[0], brow2[1]);
            unsigned long long b1p = pack2(brow2[2], brow2[3]);

            const ulonglong2* Wap = (const ulonglong2*)&S->W2a[0][0];
            const float* hrow = S->h1s[r];            // h1(t-1) — input to layer-2 step t-1
            #pragma unroll 4
            for (int k = 0; k < H1_; ++k) {
                float hv = hrow[k];
                unsigned long long hv2 = pack2(hv, hv);
                ulonglong2 w = Wap[k * 8 + tc];
                FMA2(b0p, hv2, w.x);  FMA2(b1p, hv2, w.y);
            }
            const ulonglong2* Wbp = (const ulonglong2*)&S->W2b[0][0];
            const float* h2row = S->h2s[r];           // h2(t-2)
            #pragma unroll 4
            for (int k = 0; k < H2_; ++k) {
                float hv = h2row[k];
                unsigned long long hv2 = pack2(hv, hv);
                ulonglong2 w = Wbp[k * 8 + tc];
                FMA2(b0p, hv2, w.x);  FMA2(b1p, hv2, w.y);
            }
            float2 if2 = unpack2(b0p), go2 = unpack2(b1p);
            float i2 = sigf(if2.x), f2 = sigf(if2.y), g2 = tanh_f(go2.x), o2 = sigf(go2.y);
            c2 = f2 * c2 + i2 * g2;
            g_h2buf[t & 1][B0 + r][v0 + tc] = o2 * tanh_f(c2);
        } else {
            g_h2buf[1][B0 + r][v0 + tc] = 0.0f;       // h2(0) = 0 published at t=1
        }

        // ---- publish: all writes done -> bump counter (release) ----
        __syncthreads();
        if (tid == 0) {
            __threadfence();
            atomicAdd(&g_cnt[bg], 1);
        }
    }
}

// ---- MLP head: out = relu(hT2 @ W1^T + b1) @ W2^T + b2 ----
__global__ void classifier_kernel(const float* __restrict__ W1, const float* __restrict__ b1,
                                  const float* __restrict__ W2, const float* __restrict__ b2,
                                  float* __restrict__ out)
{
    __shared__ float hrow[H2_];
    __shared__ float z[DMLP_];
    const int row = blockIdx.x;
    const int tid = threadIdx.x;   // 128

    hrow[tid] = g_h2buf[(T_ + 1) & 1][row][tid];   // final h2 lives in slot 1
    __syncthreads();

    float acc = b1[tid];
    #pragma unroll 8
    for (int k = 0; k < H2_; ++k) acc += hrow[k] * W1[tid * H2_ + k];
    z[tid] = fmaxf(acc, 0.0f);
    __syncthreads();

    if (tid < NCLS_) {
        float o = b2[tid];
        #pragma unroll 8
        for (int j = 0; j < DMLP_; ++j) o += z[j] * W2[tid * DMLP_ + j];
        out[row * NCLS_ + tid] = o;
    }
}

extern "C" void kernel_launch(void* const* d_in, const int* in_sizes, int n_in,
                              void* d_out, int out_size)
{
    (void)in_sizes; (void)n_in; (void)out_size;
    const float* x    = (const float*)d_in[0];
    const float* Wih1 = (const float*)d_in[1];
    const float* Whh1 = (const float*)d_in[2];
    const float* bih1 = (const float*)d_in[3];
    const float* bhh1 = (const float*)d_in[4];
    const float* Wih2 = (const float*)d_in[5];
    const float* Whh2 = (const float*)d_in[6];
    const float* bih2 = (const float*)d_in[7];
    const float* bhh2 = (const float*)d_in[8];
    const float* W1   = (const float*)d_in[9];
    const float* b1   = (const float*)d_in[10];
    const float* W2   = (const float*)d_in[11];
    const float* b2   = (const float*)d_in[12];
    float* out = (float*)d_out;

    cudaFuncSetAttribute(lstm_persistent,
                         cudaFuncAttributeMaxDynamicSharedMemorySize, (int)SMEM_BYTES);

    lstm_init_kernel<<<256, 256>>>();
    lstm_persistent<<<GB * GCOL, NTHR, SMEM_BYTES>>>(
        x, Wih1, Whh1, bih1, bhh1, Wih2, Whh2, bih2, bhh2);
    classifier_kernel<<<B_, DMLP_>>>(W1, b1, W2, b2, out);
}

// round 13
// speedup vs baseline: 1.0019x; 1.0006x over previous
#include <cuda_runtime.h>
#include <cstdint>

#define B_    256
#define T_    1000
#define F_    64
#define H1_   256
#define H2_   128
#define NCLS_ 5
#define DMLP_ 128

#define GCOL  16      // column groups (hidden-unit split)
#define GB    8       // batch groups
#define BC    32      // batch rows per batch group (256/8)
#define U1    16      // layer-1 hidden units per column group (256/16)
#define U2    8       // layer-2 hidden units per column group (128/16)
#define NTHR  256

// ---- global exchange state (static device arrays; no allocation) ----
__device__ float g_h1buf[2][B_][H1_];   // slot t&1 holds h1(t)
__device__ float g_h2buf[2][B_][H2_];   // slot t&1 holds h2(t-1)
__device__ int   g_cnt[GB];             // monotonic arrival counter per batch group

// ---- SMEM layout (dynamic, ~184.4 KB) ----
struct SmemLayout {
    float Wh1[H1_][U1 * 4];   // Whh1 slice, [k][j*4+g]          64 KB
    float Wx1[F_][U1 * 4];    // Wih1 slice                       16 KB
    float W2a[H1_][U2 * 4];   // Wih2 slice (input = h1)          32 KB
    float W2b[H2_][U2 * 4];   // Whh2 slice                       16 KB
    float h1s[BC][H1_];       // staged h1(t-1)                   32 KB
    float h2s[BC][H2_];       // staged h2(t-2)                   16 KB
    float xs[BC][F_];         // staged x_t                        8 KB
    float bias1[U1 * 4];
    float bias2[U2 * 4];
};
#define SMEM_BYTES (sizeof(SmemLayout))

// ---- packed fp32x2 helpers (sm_103a dual-rate fp32 path) ----
__device__ __forceinline__ unsigned long long pack2(float a, float b) {
    unsigned long long r;
    asm("mov.b64 %0, {%1, %2};" : "=l"(r) : "f"(a), "f"(b));
    return r;
}
__device__ __forceinline__ float2 unpack2(unsigned long long v) {
    float2 r;
    asm("mov.b64 {%0, %1}, %2;" : "=f"(r.x), "=f"(r.y) : "l"(v));
    return r;
}
#define FMA2(acc, a, b) \
    asm("fma.rn.f32x2 %0, %1, %2, %0;" : "+l"(acc) : "l"(a), "l"(b))

__device__ __forceinline__ float sigf(float v) {
    return 1.0f / (1.0f + __expf(-v));
}
__device__ __forceinline__ float tanh_f(float v) {
    v = fminf(fmaxf(v, -15.0f), 15.0f);   // keep __expf finite
    float e = __expf(-2.0f * v);
    return (1.0f - e) / (1.0f + e);
}

// ---- init: zero initial state + counters (runs every graph replay) ----
__global__ void lstm_init_kernel() {
    int i = blockIdx.x * blockDim.x + threadIdx.x;
    int stride = gridDim.x * blockDim.x;
    if (i < GB) g_cnt[i] = 0;
    for (int j = i; j < B_ * H1_; j += stride) ((float*)g_h1buf)[j] = 0.0f;  // slot 0
    for (int j = i; j < B_ * H2_; j += stride) ((float*)g_h2buf)[j] = 0.0f;  // slot 0 (hygiene)
}

// ---- persistent two-layer LSTM ----
extern "C" __global__ void __launch_bounds__(NTHR, 1)
lstm_persistent(const float* __restrict__ x,
                const float* __restrict__ Wih1, const float* __restrict__ Whh1,
                const float* __restrict__ bih1, const float* __restrict__ bhh1,
                const float* __restrict__ Wih2, const float* __restrict__ Whh2,
                const float* __restrict__ bih2, const float* __restrict__ bhh2)
{
    extern __shared__ float smem_raw[];
    SmemLayout* S = (SmemLayout*)smem_raw;

    const int tid = threadIdx.x;
    const int cg  = blockIdx.x & (GCOL - 1);   // column group
    const int bg  = blockIdx.x >> 4;           // batch group
    const int B0  = bg * BC;
    const int u0  = cg * U1;                   // layer-1 unit base
    const int v0  = cg * U2;                   // layer-2 unit base

    // ---- one-time weight slice load (transposed into [k][unit][gate]) ----
    for (int idx = tid; idx < H1_ * U1 * 4; idx += NTHR) {
        int k = idx >> 6, rem = idx & 63, j = rem >> 2, g = rem & 3;
        S->Wh1[k][rem] = Whh1[(g * H1_ + u0 + j) * H1_ + k];
    }
    for (int idx = tid; idx < F_ * U1 * 4; idx += NTHR) {
        int f = idx >> 6, rem = idx & 63, j = rem >> 2, g = rem & 3;
        S->Wx1[f][rem] = Wih1[(g * H1_ + u0 + j) * F_ + f];
    }
    for (int idx = tid; idx < H1_ * U2 * 4; idx += NTHR) {
        int k = idx >> 5, rem = idx & 31, j = rem >> 2, g = rem & 3;
        S->W2a[k][rem] = Wih2[(g * H2_ + v0 + j) * H1_ + k];
    }
    for (int idx = tid; idx < H2_ * U2 * 4; idx += NTHR) {
        int k = idx >> 5, rem = idx & 31, j = rem >> 2, g = rem & 3;
        S->W2b[k][rem] = Whh2[(g * H2_ + v0 + j) * H2_ + k];
    }
    if (tid < U1 * 4) {
        int j = tid >> 2, g = tid & 3;
        S->bias1[tid] = bih1[g * H1_ + u0 + j] + bhh1[g * H1_ + u0 + j];
    }
    if (tid < U2 * 4) {
        int j = tid >> 2, g = tid & 3;
        S->bias2[tid] = bih2[g * H2_ + v0 + j] + bhh2[g * H2_ + v0 + j];
    }
    __syncthreads();

    const int r  = tid >> 3;     // batch row within group (0..31)
    const int tc = tid & 7;      // column-thread (0..7)
    float c1a = 0.0f, c1b = 0.0f, c2 = 0.0f;   // cell states, register-resident

    // iteration t: layer-1 step t (t<=T), layer-2 step t-1 (t>=2)
    for (int t = 1; t <= T_ + 1; ++t) {
        // ---- wait for all 16 column CTAs to have published step t-1 ----
        if (t > 1) {
            const int target = GCOL * (t - 1);
            if (tid == 0) {
                int v;
                do {
                    asm volatile("ld.acquire.gpu.u32 %0, [%1];"
                                 : "=r"(v) : "l"(&g_cnt[bg]) : "memory");
                } while (v < target);
                __threadfence();
            }
            __syncthreads();
        }
        const int rslot = (t - 1) & 1;

        // ---- stage h1(t-1), h2(t-2), x_t into SMEM ----
        {
            const float4* s1 = (const float4*)&g_h1buf[rslot][B0][0];
            float4* d1 = (float4*)&S->h1s[0][0];
            for (int i = tid; i < BC * H1_ / 4; i += NTHR) d1[i] = s1[i];
            const float4* s2 = (const float4*)&g_h2buf[rslot][B0][0];
            float4* d2 = (float4*)&S->h2s[0][0];
            for (int i = tid; i < BC * H2_ / 4; i += NTHR) d2[i] = s2[i];
            if (t <= T_) {
                float4* dx = (float4*)&S->xs[0][0];
                for (int i = tid; i < BC * F_ / 4; i += NTHR) {
                    int row = i >> 4, col = i & 15;
                    const float4* sx = (const float4*)(x + (size_t)(B0 + row) * T_ * F_
                                                         + (size_t)(t - 1) * F_);
                    dx[i] = sx[col];
                }
            }
        }
        __syncthreads();

        // ---- layer 1: gates for 2 units (j0 = 2*tc, j0+1), 1 batch row ----
        if (t <= T_) {
            const int base = 2 * tc;
            const float* brow = &S->bias1[base * 4];
            unsigned long long a0 = pack2(brow[0], brow[1]);
            unsigned long long a1 = pack2(brow[2], brow[3]);
            unsigned long long a2 = pack2(brow[4], brow[5]);
            unsigned long long a3 = pack2(brow[6], brow[7]);

            const ulonglong2* Wp = (const ulonglong2*)&S->Wh1[0][0];
            const float* hrow = S->h1s[r];
            #pragma unroll 4
            for (int k = 0; k < H1_; ++k) {
                float hv = hrow[k];
                unsigned long long hv2 = pack2(hv, hv);
                ulonglong2 wA = Wp[k * 16 + base];
                ulonglong2 wB = Wp[k * 16 + base + 1];
                FMA2(a0, hv2, wA.x);  FMA2(a1, hv2, wA.y);
                FMA2(a2, hv2, wB.x);  FMA2(a3, hv2, wB.y);
            }
            const ulonglong2* Wxp = (const ulonglong2*)&S->Wx1[0][0];
            const float* xrow = S->xs[r];
            #pragma unroll 4
            for (int f = 0; f < F_; ++f) {
                float xv = xrow[f];
                unsigned long long xv2 = pack2(xv, xv);
                ulonglong2 wA = Wxp[f * 16 + base];
                ulonglong2 wB = Wxp[f * 16 + base + 1];
                FMA2(a0, xv2, wA.x);  FMA2(a1, xv2, wA.y);
                FMA2(a2, xv2, wB.x);  FMA2(a3, xv2, wB.y);
            }

            float2 if0 = unpack2(a0), go0 = unpack2(a1);
            float2 if1 = unpack2(a2), go1 = unpack2(a3);
            float i0 = sigf(if0.x), f0 = sigf(if0.y), g0 = tanh_f(go0.x), o0 = sigf(go0.y);
            c1a = f0 * c1a + i0 * g0;
            float h0 = o0 * tanh_f(c1a);
            float i1 = sigf(if1.x), f1 = sigf(if1.y), g1 = tanh_f(go1.x), o1 = sigf(go1.y);
            c1b = f1 * c1b + i1 * g1;
            float h1v = o1 * tanh_f(c1b);
            *(float2*)&g_h1buf[t & 1][B0 + r][u0 + base] = make_float2(h0, h1v);
        }

        // ---- layer 2 (one step behind): unit v0+tc, 1 batch row ----
        if (t >= 2) {
            const float* brow2 = &S->bias2[tc * 4];
            unsigned long long b0p = pack2(brow2[0], brow2[1]);
            unsigned long long b1p = pack2(brow2[2], brow2[3]);

            const ulonglong2* Wap = (const ulonglong2*)&S->W2a[0][0];
            const float* hrow = S->h1s[r];            // h1(t-1) — input to layer-2 step t-1
            #pragma unroll 4
            for (int k = 0; k < H1_; ++k) {
                float hv = hrow[k];
                unsigned long long hv2 = pack2(hv, hv);
                ulonglong2 w = Wap[k * 8 + tc];
                FMA2(b0p, hv2, w.x);  FMA2(b1p, hv2, w.y);
            }
            const ulonglong2* Wbp = (const ulonglong2*)&S->W2b[0][0];
            const float* h2row = S->h2s[r];           // h2(t-2)
            #pragma unroll 4
            for (int k = 0; k < H2_; ++k) {
                float hv = h2row[k];
                unsigned long long hv2 = pack2(hv, hv);
                ulonglong2 w = Wbp[k * 8 + tc];
                FMA2(b0p, hv2, w.x);  FMA2(b1p, hv2, w.y);
            }
            float2 if2 = unpack2(b0p), go2 = unpack2(b1p);
            float i2 = sigf(if2.x), f2 = sigf(if2.y), g2 = tanh_f(go2.x), o2 = sigf(go2.y);
            c2 = f2 * c2 + i2 * g2;
            g_h2buf[t & 1][B0 + r][v0 + tc] = o2 * tanh_f(c2);
        } else {
            g_h2buf[1][B0 + r][v0 + tc] = 0.0f;       // h2(0) = 0 published at t=1
        }

        // ---- publish: all writes done -> bump counter (release) ----
        __syncthreads();
        if (tid == 0) {
            __threadfence();
            atomicAdd(&g_cnt[bg], 1);
        }
    }
}

// ---- MLP head: out = relu(hT2 @ W1^T + b1) @ W2^T + b2 ----
__global__ void classifier_kernel(const float* __restrict__ W1, const float* __restrict__ b1,
                                  const float* __restrict__ W2, const float* __restrict__ b2,
                                  float* __restrict__ out)
{
    __shared__ float hrow[H2_];
    __shared__ float z[DMLP_];
    const int row = blockIdx.x;
    const int tid = threadIdx.x;   // 128

    hrow[tid] = g_h2buf[(T_ + 1) & 1][row][tid];   // final h2 lives in slot 1
    __syncthreads();

    float acc = b1[tid];
    #pragma unroll 8
    for (int k = 0; k < H2_; ++k) acc += hrow[k] * W1[tid * H2_ + k];
    z[tid] = fmaxf(acc, 0.0f);
    __syncthreads();

    if (tid < NCLS_) {
        float o = b2[tid];
        #pragma unroll 8
        for (int j = 0; j < DMLP_; ++j) o += z[j] * W2[tid * DMLP_ + j];
        out[row * NCLS_ + tid] = o;
    }
}

extern "C" void kernel_launch(void* const* d_in, const int* in_sizes, int n_in,
                              void* d_out, int out_size)
{
    (void)in_sizes; (void)n_in; (void)out_size;
    const float* x    = (const float*)d_in[0];
    const float* Wih1 = (const float*)d_in[1];
    const float* Whh1 = (const float*)d_in[2];
    const float* bih1 = (const float*)d_in[3];
    const float* bhh1 = (const float*)d_in[4];
    const float* Wih2 = (const float*)d_in[5];
    const float* Whh2 = (const float*)d_in[6];
    const float* bih2 = (const float*)d_in[7];
    const float* bhh2 = (const float*)d_in[8];
    const float* W1   = (const float*)d_in[9];
    const float* b1   = (const float*)d_in[10];
    const float* W2   = (const float*)d_in[11];
    const float* b2   = (const float*)d_in[12];
    float* out = (float*)d_out;

    cudaFuncSetAttribute(lstm_persistent,
                         cudaFuncAttributeMaxDynamicSharedMemorySize, (int)SMEM_BYTES);

    lstm_init_kernel<<<256, 256>>>();
    lstm_persistent<<<GB * GCOL, NTHR, SMEM_BYTES>>>(
        x, Wih1, Whh1, bih1, bhh1, Wih2, Whh2, bih2, bhh2);
    classifier_kernel<<<B_, DMLP_>>>(W1, b1, W2, b2, out);
}

// round 14
// speedup vs baseline: 1.0020x; 1.0001x over previous
#include <cuda_runtime.h>
#include <cstdint>

#define B_    256
#define T_    1000
#define F_    64
#define H1_   256
#define H2_   128
#define NCLS_ 5
#define DMLP_ 128

#define GCOL  16      // column groups (hidden-unit split)
#define GB    8       // batch groups
#define BC    32      // batch rows per batch group (256/8)
#define U1    16      // layer-1 hidden units per column group (256/16)
#define U2    8       // layer-2 hidden units per column group (128/16)
#define NTHR  256

// ---- global exchange state (static device arrays; no allocation) ----
__device__ float g_h1buf[2][B_][H1_];   // slot t&1 holds h1(t)
__device__ float g_h2buf[2][B_][H2_];   // slot t&1 holds h2(t-1)
__device__ int   g_cnt[GB];             // monotonic arrival counter per batch group

// ---- SMEM layout (dynamic, ~184.4 KB) ----
struct SmemLayout {
    float Wh1[H1_][U1 * 4];   // Whh1 slice, [k][j*4+g]          64 KB
    float Wx1[F_][U1 * 4];    // Wih1 slice                       16 KB
    float W2a[H1_][U2 * 4];   // Wih2 slice (input = h1)          32 KB
    float W2b[H2_][U2 * 4];   // Whh2 slice                       16 KB
    float h1s[BC][H1_];       // staged h1(t-1)                   32 KB
    float h2s[BC][H2_];       // staged h2(t-2)                   16 KB
    float xs[BC][F_];         // staged x_t                        8 KB
    float bias1[U1 * 4];
    float bias2[U2 * 4];
};
#define SMEM_BYTES (sizeof(SmemLayout))

// ---- packed fp32x2 helpers (sm_103a dual-rate fp32 path) ----
__device__ __forceinline__ unsigned long long pack2(float a, float b) {
    unsigned long long r;
    asm("mov.b64 %0, {%1, %2};" : "=l"(r) : "f"(a), "f"(b));
    return r;
}
__device__ __forceinline__ float2 unpack2(unsigned long long v) {
    float2 r;
    asm("mov.b64 {%0, %1}, %2;" : "=f"(r.x), "=f"(r.y) : "l"(v));
    return r;
}
#define FMA2(acc, a, b) \
    asm("fma.rn.f32x2 %0, %1, %2, %0;" : "+l"(acc) : "l"(a), "l"(b))

__device__ __forceinline__ float sigf(float v) {
    return 1.0f / (1.0f + __expf(-v));
}
__device__ __forceinline__ float tanh_f(float v) {
    v = fminf(fmaxf(v, -15.0f), 15.0f);   // keep __expf finite
    float e = __expf(-2.0f * v);
    return (1.0f - e) / (1.0f + e);
}

// ---- init: zero initial state + counters (runs every graph replay) ----
__global__ void lstm_init_kernel() {
    int i = blockIdx.x * blockDim.x + threadIdx.x;
    int stride = gridDim.x * blockDim.x;
    if (i < GB) g_cnt[i] = 0;
    for (int j = i; j < B_ * H1_; j += stride) ((float*)g_h1buf)[j] = 0.0f;  // slot 0
    for (int j = i; j < B_ * H2_; j += stride) ((float*)g_h2buf)[j] = 0.0f;  // slot 0 (hygiene)
}

// ---- persistent two-layer LSTM ----
extern "C" __global__ void __launch_bounds__(NTHR, 1)
lstm_persistent(const float* __restrict__ x,
                const float* __restrict__ Wih1, const float* __restrict__ Whh1,
                const float* __restrict__ bih1, const float* __restrict__ bhh1,
                const float* __restrict__ Wih2, const float* __restrict__ Whh2,
                const float* __restrict__ bih2, const float* __restrict__ bhh2)
{
    extern __shared__ float smem_raw[];
    SmemLayout* S = (SmemLayout*)smem_raw;

    const int tid = threadIdx.x;
    const int cg  = blockIdx.x & (GCOL - 1);   // column group
    const int bg  = blockIdx.x >> 4;           // batch group
    const int B0  = bg * BC;
    const int u0  = cg * U1;                   // layer-1 unit base
    const int v0  = cg * U2;                   // layer-2 unit base

    // ---- one-time weight slice load (transposed into [k][unit][gate]) ----
    for (int idx = tid; idx < H1_ * U1 * 4; idx += NTHR) {
        int k = idx >> 6, rem = idx & 63, j = rem >> 2, g = rem & 3;
        S->Wh1[k][rem] = Whh1[(g * H1_ + u0 + j) * H1_ + k];
    }
    for (int idx = tid; idx < F_ * U1 * 4; idx += NTHR) {
        int f = idx >> 6, rem = idx & 63, j = rem >> 2, g = rem & 3;
        S->Wx1[f][rem] = Wih1[(g * H1_ + u0 + j) * F_ + f];
    }
    for (int idx = tid; idx < H1_ * U2 * 4; idx += NTHR) {
        int k = idx >> 5, rem = idx & 31, j = rem >> 2, g = rem & 3;
        S->W2a[k][rem] = Wih2[(g * H2_ + v0 + j) * H1_ + k];
    }
    for (int idx = tid; idx < H2_ * U2 * 4; idx += NTHR) {
        int k = idx >> 5, rem = idx & 31, j = rem >> 2, g = rem & 3;
        S->W2b[k][rem] = Whh2[(g * H2_ + v0 + j) * H2_ + k];
    }
    if (tid < U1 * 4) {
        int j = tid >> 2, g = tid & 3;
        S->bias1[tid] = bih1[g * H1_ + u0 + j] + bhh1[g * H1_ + u0 + j];
    }
    if (tid < U2 * 4) {
        int j = tid >> 2, g = tid & 3;
        S->bias2[tid] = bih2[g * H2_ + v0 + j] + bhh2[g * H2_ + v0 + j];
    }
    __syncthreads();

    const int r  = tid >> 3;     // batch row within group (0..31)
    const int tc = tid & 7;      // column-thread (0..7)
    float c1a = 0.0f, c1b = 0.0f, c2 = 0.0f;   // cell states, register-resident

    // iteration t: layer-1 step t (t<=T), layer-2 step t-1 (t>=2)
    for (int t = 1; t <= T_ + 1; ++t) {
        // ---- wait for all 16 column CTAs to have published step t-1 ----
        if (t > 1) {
            const int target = GCOL * (t - 1);
            if (tid == 0) {
                int v;
                do {
                    asm volatile("ld.acquire.gpu.u32 %0, [%1];"
                                 : "=r"(v) : "l"(&g_cnt[bg]) : "memory");
                } while (v < target);
                __threadfence();
            }
            __syncthreads();
        }
        const int rslot = (t - 1) & 1;

        // ---- stage h1(t-1), h2(t-2), x_t into SMEM ----
        {
            const float4* s1 = (const float4*)&g_h1buf[rslot][B0][0];
            float4* d1 = (float4*)&S->h1s[0][0];
            for (int i = tid; i < BC * H1_ / 4; i += NTHR) d1[i] = s1[i];
            const float4* s2 = (const float4*)&g_h2buf[rslot][B0][0];
            float4* d2 = (float4*)&S->h2s[0][0];
            for (int i = tid; i < BC * H2_ / 4; i += NTHR) d2[i] = s2[i];
            if (t <= T_) {
                float4* dx = (float4*)&S->xs[0][0];
                for (int i = tid; i < BC * F_ / 4; i += NTHR) {
                    int row = i >> 4, col = i & 15;
                    const float4* sx = (const float4*)(x + (size_t)(B0 + row) * T_ * F_
                                                         + (size_t)(t - 1) * F_);
                    dx[i] = sx[col];
                }
            }
        }
        __syncthreads();

        // ---- layer 1: gates for 2 units (j0 = 2*tc, j0+1), 1 batch row ----
        if (t <= T_) {
            const int base = 2 * tc;
            const float* brow = &S->bias1[base * 4];
            unsigned long long a0 = pack2(brow[0], brow[1]);
            unsigned long long a1 = pack2(brow[2], brow[3]);
            unsigned long long a2 = pack2(brow[4], brow[5]);
            unsigned long long a3 = pack2(brow[6], brow[7]);

            const ulonglong2* Wp = (const ulonglong2*)&S->Wh1[0][0];
            const float* hrow = S->h1s[r];
            #pragma unroll 4
            for (int k = 0; k < H1_; ++k) {
                float hv = hrow[k];
                unsigned long long hv2 = pack2(hv, hv);
                ulonglong2 wA = Wp[k * 16 + base];
                ulonglong2 wB = Wp[k * 16 + base + 1];
                FMA2(a0, hv2, wA.x);  FMA2(a1, hv2, wA.y);
                FMA2(a2, hv2, wB.x);  FMA2(a3, hv2, wB.y);
            }
            const ulonglong2* Wxp = (const ulonglong2*)&S->Wx1[0][0];
            const float* xrow = S->xs[r];
            #pragma unroll 4
            for (int f = 0; f < F_; ++f) {
                float xv = xrow[f];
                unsigned long long xv2 = pack2(xv, xv);
                ulonglong2 wA = Wxp[f * 16 + base];
                ulonglong2 wB = Wxp[f * 16 + base + 1];
                FMA2(a0, xv2, wA.x);  FMA2(a1, xv2, wA.y);
                FMA2(a2, xv2, wB.x);  FMA2(a3, xv2, wB.y);
            }

            float2 if0 = unpack2(a0), go0 = unpack2(a1);
            float2 if1 = unpack2(a2), go1 = unpack2(a3);
            float i0 = sigf(if0.x), f0 = sigf(if0.y), g0 = tanh_f(go0.x), o0 = sigf(go0.y);
            c1a = f0 * c1a + i0 * g0;
            float h0 = o0 * tanh_f(c1a);
            float i1 = sigf(if1.x), f1 = sigf(if1.y), g1 = tanh_f(go1.x), o1 = sigf(go1.y);
            c1b = f1 * c1b + i1 * g1;
            float h1v = o1 * tanh_f(c1b);
            *(float2*)&g_h1buf[t & 1][B0 + r][u0 + base] = make_float2(h0, h1v);
        }

        // ---- layer 2 (one step behind): unit v0+tc, 1 batch row ----
        if (t >= 2) {
            const float* brow2 = &S->bias2[tc * 4];
            unsigned long long b0p = pack2(brow2[0], brow2[1]);
            unsigned long long b1p = pack2(brow2[2], brow2[3]);

            const ulonglong2* Wap = (const ulonglong2*)&S->W2a[0][0];
            const float* hrow = S->h1s[r];            // h1(t-1) — input to layer-2 step t-1
            #pragma unroll 4
            for (int k = 0; k < H1_; ++k) {
                float hv = hrow[k];
                unsigned long long hv2 = pack2(hv, hv);
                ulonglong2 w = Wap[k * 8 + tc];
                FMA2(b0p, hv2, w.x);  FMA2(b1p, hv2, w.y);
            }
            const ulonglong2* Wbp = (const ulonglong2*)&S->W2b[0][0];
            const float* h2row = S->h2s[r];           // h2(t-2)
            #pragma unroll 4
            for (int k = 0; k < H2_; ++k) {
                float hv = h2row[k];
                unsigned long long hv2 = pack2(hv, hv);
                ulonglong2 w = Wbp[k * 8 + tc];
                FMA2(b0p, hv2, w.x);  FMA2(b1p, hv2, w.y);
            }
            float2 if2 = unpack2(b0p), go2 = unpack2(b1p);
            float i2 = sigf(if2.x), f2 = sigf(if2.y), g2 = tanh_f(go2.x), o2 = sigf(go2.y);
            c2 = f2 * c2 + i2 * g2;
            g_h2buf[t & 1][B0 + r][v0 + tc] = o2 * tanh_f(c2);
        } else {
            g_h2buf[1][B0 + r][v0 + tc] = 0.0f;       // h2(0) = 0 published at t=1
        }

        // ---- publish: all writes done -> bump counter (release) ----
        __syncthreads();
        if (tid == 0) {
            __threadfence();
            atomicAdd(&g_cnt[bg], 1);
        }
    }
}

// ---- MLP head: out = relu(hT2 @ W1^T + b1) @ W2^T + b2 ----
__global__ void classifier_kernel(const float* __restrict__ W1, const float* __restrict__ b1,
                                  const float* __restrict__ W2, const float* __restrict__ b2,
                                  float* __restrict__ out)
{
    __shared__ float hrow[H2_];
    __shared__ float z[DMLP_];
    const int row = blockIdx.x;
    const int tid = threadIdx.x;   // 128

    hrow[tid] = g_h2buf[(T_ + 1) & 1][row][tid];   // final h2 lives in slot 1
    __syncthreads();

    float acc = b1[tid];
    #pragma unroll 8
    for (int k = 0; k < H2_; ++k) acc += hrow[k] * W1[tid * H2_ + k];
    z[tid] = fmaxf(acc, 0.0f);
    __syncthreads();

    if (tid < NCLS_) {
        float o = b2[tid];
        #pragma unroll 8
        for (int j = 0; j < DMLP_; ++j) o += z[j] * W2[tid * DMLP_ + j];
        out[row * NCLS_ + tid] = o;
    }
}

extern "C" void kernel_launch(void* const* d_in, const int* in_sizes, int n_in,
                              void* d_out, int out_size)
{
    (void)in_sizes; (void)n_in; (void)out_size;
    const float* x    = (const float*)d_in[0];
    const float* Wih1 = (const float*)d_in[1];
    const float* Whh1 = (const float*)d_in[2];
    const float* bih1 = (const float*)d_in[3];
    const float* bhh1 = (const float*)d_in[4];
    const float* Wih2 = (const float*)d_in[5];
    const float* Whh2 = (const float*)d_in[6];
    const float* bih2 = (const float*)d_in[7];
    const float* bhh2 = (const float*)d_in[8];
    const float* W1   = (const float*)d_in[9];
    const float* b1   = (const float*)d_in[10];
    const float* W2   = (const float*)d_in[11];
    const float* b2   = (const float*)d_in[12];
    float* out = (float*)d_out;

    cudaFuncSetAttribute(lstm_persistent,
                         cudaFuncAttributeMaxDynamicSharedMemorySize, (int)SMEM_BYTES);

    lstm_init_kernel<<<256, 256>>>();
    lstm_persistent<<<GB * GCOL, NTHR, SMEM_BYTES>>>(
        x, Wih1, Whh1, bih1, bhh1, Wih2, Whh2, bih2, bhh2);
    classifier_kernel<<<B_, DMLP_>>>(W1, b1, W2, b2, out);
}

// round 15
// speedup vs baseline: 2.3870x; 2.3823x over previous
#include <cuda_runtime.h>
#include <cstdint>

#define B_    256
#define T_    1000
#define F_    64
#define H1_   256
#define H2_   128
#define NCLS_ 5
#define DMLP_ 128

#define GCOL  16      // column groups (hidden-unit split)
#define GB    8       // batch groups
#define BC    32      // batch rows per batch group (256/8)
#define U1    16      // layer-1 hidden units per column group
#define U2    8       // layer-2 hidden units per column group
#define NTHR  256

// padded SMEM strides (floats): stride*4 bytes ≡ 16 mod 128 → bank offset 4 per row
#define H1P   260
#define H2P   132
#define FP_   68

// ---- global exchange state ----
__device__ float g_h1buf[2][B_][H1_];   // slot t&1 holds h1(t)
__device__ float g_h2buf[2][B_][H2_];   // slot t&1 holds h2(t-1)
__device__ int   g_cnt[GB];             // monotonic arrival counter per batch group

// ---- SMEM layout (~187 KB) ----
struct SmemLayout {
    float Wh1[H1_][U1 * 4];   // Whh1 slice, [k][unit*4+gate]   64 KB
    float Wx1[F_][U1 * 4];    // Wih1 slice                      16 KB
    float W2a[H1_][U2 * 4];   // Wih2 slice (input = h1)         32 KB
    float W2b[H2_][U2 * 4];   // Whh2 slice                      16 KB
    float h1s[BC][H1P];       // staged h1(t-1), padded          32.5 KB
    float h2s[BC][H2P];       // staged h2(t-2), padded          16.5 KB
    float xs[BC][FP_];        // staged x_t, padded               8.5 KB
    float bias1[U1 * 4];
    float bias2[U2 * 4];
};
#define SMEM_BYTES (sizeof(SmemLayout))

// ---- packed fp32x2 helpers ----
__device__ __forceinline__ unsigned long long pack2(float a, float b) {
    unsigned long long r;
    asm("mov.b64 %0, {%1, %2};" : "=l"(r) : "f"(a), "f"(b));
    return r;
}
__device__ __forceinline__ float2 unpack2(unsigned long long v) {
    float2 r;
    asm("mov.b64 {%0, %1}, %2;" : "=f"(r.x), "=f"(r.y) : "l"(v));
    return r;
}
#define FMA2(acc, a, b) \
    asm("fma.rn.f32x2 %0, %1, %2, %0;" : "+l"(acc) : "l"(a), "l"(b))

__device__ __forceinline__ float sigf(float v) {
    return 1.0f / (1.0f + __expf(-v));
}
__device__ __forceinline__ float tanh_f(float v) {
    v = fminf(fmaxf(v, -15.0f), 15.0f);
    float e = __expf(-2.0f * v);
    return (1.0f - e) / (1.0f + e);
}

// ---- init: zero initial state + counters (runs every graph replay) ----
__global__ void lstm_init_kernel() {
    int i = blockIdx.x * blockDim.x + threadIdx.x;
    int stride = gridDim.x * blockDim.x;
    if (i < GB) g_cnt[i] = 0;
    for (int j = i; j < B_ * H1_; j += stride) ((float*)g_h1buf)[j] = 0.0f;  // slot 0
    for (int j = i; j < B_ * H2_; j += stride) ((float*)g_h2buf)[j] = 0.0f;  // slot 0
}

// ---- persistent two-layer LSTM ----
extern "C" __global__ void __launch_bounds__(NTHR, 1)
lstm_persistent(const float* __restrict__ x,
                const float* __restrict__ Wih1, const float* __restrict__ Whh1,
                const float* __restrict__ bih1, const float* __restrict__ bhh1,
                const float* __restrict__ Wih2, const float* __restrict__ Whh2,
                const float* __restrict__ bih2, const float* __restrict__ bhh2)
{
    extern __shared__ float smem_raw[];
    SmemLayout* S = (SmemLayout*)smem_raw;

    const int tid = threadIdx.x;
    const int cg  = blockIdx.x & (GCOL - 1);
    const int bg  = blockIdx.x >> 4;
    const int B0  = bg * BC;
    const int u0  = cg * U1;
    const int v0  = cg * U2;

    // ---- one-time weight slice load ([k][unit*4+gate]) ----
    for (int idx = tid; idx < H1_ * U1 * 4; idx += NTHR) {
        int k = idx >> 6, rem = idx & 63, j = rem >> 2, g = rem & 3;
        S->Wh1[k][rem] = Whh1[(g * H1_ + u0 + j) * H1_ + k];
    }
    for (int idx = tid; idx < F_ * U1 * 4; idx += NTHR) {
        int f = idx >> 6, rem = idx & 63, j = rem >> 2, g = rem & 3;
        S->Wx1[f][rem] = Wih1[(g * H1_ + u0 + j) * F_ + f];
    }
    for (int idx = tid; idx < H1_ * U2 * 4; idx += NTHR) {
        int k = idx >> 5, rem = idx & 31, j = rem >> 2, g = rem & 3;
        S->W2a[k][rem] = Wih2[(g * H2_ + v0 + j) * H1_ + k];
    }
    for (int idx = tid; idx < H2_ * U2 * 4; idx += NTHR) {
        int k = idx >> 5, rem = idx & 31, j = rem >> 2, g = rem & 3;
        S->W2b[k][rem] = Whh2[(g * H2_ + v0 + j) * H2_ + k];
    }
    if (tid < U1 * 4) {
        int j = tid >> 2, g = tid & 3;
        S->bias1[tid] = bih1[g * H1_ + u0 + j] + bhh1[g * H1_ + u0 + j];
    }
    if (tid < U2 * 4) {
        int j = tid >> 2, g = tid & 3;
        S->bias2[tid] = bih2[g * H2_ + v0 + j] + bhh2[g * H2_ + v0 + j];
    }
    __syncthreads();

    // ---- thread mapping ----
    // layer 1: warp wN covers units {2wN, 2wN+1} x 32 rows.
    //          lane: us = lane>>4 (unit sub), rs = lane&15 (rows rs, rs+16)
    // layer 2: warp wN covers unit wN x 32 rows (row = lane)
    const int wN   = tid >> 5;
    const int lane = tid & 31;
    const int us   = lane >> 4;
    const int rs   = lane & 15;
    const int u1i  = 2 * wN + us;      // layer-1 unit within CTA

    float c1A = 0.0f, c1B = 0.0f, c2 = 0.0f;   // cell states (registers)

    const ulonglong2 bv1 = *(const ulonglong2*)&S->bias1[u1i * 4];
    const ulonglong2 bv2 = *(const ulonglong2*)&S->bias2[wN * 4];

    const ulonglong2* __restrict__ Wp  = (const ulonglong2*)S->Wh1;
    const ulonglong2* __restrict__ Wxp = (const ulonglong2*)S->Wx1;
    const ulonglong2* __restrict__ Wap = (const ulonglong2*)S->W2a;
    const ulonglong2* __restrict__ Wbp = (const ulonglong2*)S->W2b;

    // iteration t: layer-1 step t (t<=T), layer-2 step t-1 (t>=2)
    for (int t = 1; t <= T_ + 1; ++t) {
        // ---- wait for all 16 column CTAs of this batch group (step t-1) ----
        if (t > 1) {
            const int target = GCOL * (t - 1);
            if (tid == 0) {
                int v;
                do {
                    asm volatile("ld.acquire.gpu.u32 %0, [%1];"
                                 : "=r"(v) : "l"(&g_cnt[bg]) : "memory");
                } while (v < target);
            }
            __syncthreads();
        }
        const int rslot = (t - 1) & 1;

        // ---- stage x_t (DRAM, issue first), then h1(t-1), h2(t-2) via .cg ----
        if (t <= T_) {
            for (int i = tid; i < BC * F_ / 4; i += NTHR) {
                int row = i >> 4, col = i & 15;
                const float4* sx = (const float4*)(x + (size_t)(B0 + row) * T_ * F_
                                                     + (size_t)(t - 1) * F_);
                *(float4*)&S->xs[row][col * 4] = __ldg(&sx[col]);
            }
        }
        {
            const float4* s1 = (const float4*)&g_h1buf[rslot][B0][0];
            for (int i = tid; i < BC * H1_ / 4; i += NTHR) {
                int row = i >> 6, col = i & 63;
                *(float4*)&S->h1s[row][col * 4] = __ldcg(&s1[i]);
            }
            const float4* s2 = (const float4*)&g_h2buf[rslot][B0][0];
            for (int i = tid; i < BC * H2_ / 4; i += NTHR) {
                int row = i >> 5, col = i & 31;
                *(float4*)&S->h2s[row][col * 4] = __ldcg(&s2[i]);
            }
        }
        __syncthreads();

        // ---- layer 1: unit u1i, rows rs and rs+16 ----
        if (t <= T_) {
            unsigned long long aA0 = bv1.x, aA1 = bv1.y;
            unsigned long long aB0 = bv1.x, aB1 = bv1.y;

            const float4* hA4 = (const float4*)&S->h1s[rs][0];
            const float4* hB4 = (const float4*)&S->h1s[rs + 16][0];
            #pragma unroll 2
            for (int k4 = 0; k4 < H1_ / 4; ++k4) {
                float4 hA = hA4[k4], hB = hB4[k4];
                float ha[4] = {hA.x, hA.y, hA.z, hA.w};
                float hb[4] = {hB.x, hB.y, hB.z, hB.w};
                #pragma unroll
                for (int j = 0; j < 4; ++j) {
                    ulonglong2 w = Wp[(k4 * 4 + j) * 16 + u1i];
                    unsigned long long a2 = pack2(ha[j], ha[j]);
                    unsigned long long b2 = pack2(hb[j], hb[j]);
                    FMA2(aA0, a2, w.x);  FMA2(aA1, a2, w.y);
                    FMA2(aB0, b2, w.x);  FMA2(aB1, b2, w.y);
                }
            }
            const float4* xA4 = (const float4*)&S->xs[rs][0];
            const float4* xB4 = (const float4*)&S->xs[rs + 16][0];
            #pragma unroll 2
            for (int k4 = 0; k4 < F_ / 4; ++k4) {
                float4 hA = xA4[k4], hB = xB4[k4];
                float ha[4] = {hA.x, hA.y, hA.z, hA.w};
                float hb[4] = {hB.x, hB.y, hB.z, hB.w};
                #pragma unroll
                for (int j = 0; j < 4; ++j) {
                    ulonglong2 w = Wxp[(k4 * 4 + j) * 16 + u1i];
                    unsigned long long a2 = pack2(ha[j], ha[j]);
                    unsigned long long b2 = pack2(hb[j], hb[j]);
                    FMA2(aA0, a2, w.x);  FMA2(aA1, a2, w.y);
                    FMA2(aB0, b2, w.x);  FMA2(aB1, b2, w.y);
                }
            }

            float2 ifA = unpack2(aA0), goA = unpack2(aA1);
            float iA = sigf(ifA.x), fA = sigf(ifA.y), gA = tanh_f(goA.x), oA = sigf(goA.y);
            c1A = fA * c1A + iA * gA;
            g_h1buf[t & 1][B0 + rs][u0 + u1i]      = oA * tanh_f(c1A);

            float2 ifB = unpack2(aB0), goB = unpack2(aB1);
            float iB = sigf(ifB.x), fB = sigf(ifB.y), gB = tanh_f(goB.x), oB = sigf(goB.y);
            c1B = fB * c1B + iB * gB;
            g_h1buf[t & 1][B0 + rs + 16][u0 + u1i] = oB * tanh_f(c1B);
        }

        // ---- layer 2 (one step behind): unit wN, row lane ----
        if (t >= 2) {
            unsigned long long g0 = bv2.x, g1 = bv2.y;

            const float4* h4 = (const float4*)&S->h1s[lane][0];   // h1(t-1)
            #pragma unroll 2
            for (int k4 = 0; k4 < H1_ / 4; ++k4) {
                float4 h = h4[k4];
                float hh[4] = {h.x, h.y, h.z, h.w};
                #pragma unroll
                for (int j = 0; j < 4; ++j) {
                    ulonglong2 w = Wap[(k4 * 4 + j) * 8 + wN];
                    unsigned long long hv2 = pack2(hh[j], hh[j]);
                    FMA2(g0, hv2, w.x);  FMA2(g1, hv2, w.y);
                }
            }
            const float4* c4 = (const float4*)&S->h2s[lane][0];   // h2(t-2)
            #pragma unroll 2
            for (int k4 = 0; k4 < H2_ / 4; ++k4) {
                float4 h = c4[k4];
                float hh[4] = {h.x, h.y, h.z, h.w};
                #pragma unroll
                for (int j = 0; j < 4; ++j) {
                    ulonglong2 w = Wbp[(k4 * 4 + j) * 8 + wN];
                    unsigned long long hv2 = pack2(hh[j], hh[j]);
                    FMA2(g0, hv2, w.x);  FMA2(g1, hv2, w.y);
                }
            }
            float2 if2 = unpack2(g0), go2 = unpack2(g1);
            float i2 = sigf(if2.x), f2 = sigf(if2.y), g2 = tanh_f(go2.x), o2 = sigf(go2.y);
            c2 = f2 * c2 + i2 * g2;
            g_h2buf[t & 1][B0 + lane][v0 + wN] = o2 * tanh_f(c2);
        } else {
            g_h2buf[1][B0 + lane][v0 + wN] = 0.0f;   // h2(0) published at t=1
        }

        // ---- publish: release-ordered counter bump ----
        __syncthreads();
        if (tid == 0) {
            asm volatile("red.release.gpu.global.add.u32 [%0], %1;"
                         :: "l"(&g_cnt[bg]), "r"(1) : "memory");
        }
    }
}

// ---- MLP head: out = relu(hT2 @ W1^T + b1) @ W2^T + b2 ----
__global__ void classifier_kernel(const float* __restrict__ W1, const float* __restrict__ b1,
                                  const float* __restrict__ W2, const float* __restrict__ b2,
                                  float* __restrict__ out)
{
    __shared__ float hrow[H2_];
    __shared__ float z[DMLP_];
    const int row = blockIdx.x;
    const int tid = threadIdx.x;   // 128

    hrow[tid] = g_h2buf[(T_ + 1) & 1][row][tid];   // final h2 lives in slot 1
    __syncthreads();

    float acc = b1[tid];
    #pragma unroll 8
    for (int k = 0; k < H2_; ++k) acc += hrow[k] * W1[tid * H2_ + k];
    z[tid] = fmaxf(acc, 0.0f);
    __syncthreads();

    if (tid < NCLS_) {
        float o = b2[tid];
        #pragma unroll 8
        for (int j = 0; j < DMLP_; ++j) o += z[j] * W2[tid * DMLP_ + j];
        out[row * NCLS_ + tid] = o;
    }
}

extern "C" void kernel_launch(void* const* d_in, const int* in_sizes, int n_in,
                              void* d_out, int out_size)
{
    (void)in_sizes; (void)n_in; (void)out_size;
    const float* x    = (const float*)d_in[0];
    const float* Wih1 = (const float*)d_in[1];
    const float* Whh1 = (const float*)d_in[2];
    const float* bih1 = (const float*)d_in[3];
    const float* bhh1 = (const float*)d_in[4];
    const float* Wih2 = (const float*)d_in[5];
    const float* Whh2 = (const float*)d_in[6];
    const float* bih2 = (const float*)d_in[7];
    const float* bhh2 = (const float*)d_in[8];
    const float* W1   = (const float*)d_in[9];
    const float* b1   = (const float*)d_in[10];
    const float* W2   = (const float*)d_in[11];
    const float* b2   = (const float*)d_in[12];
    float* out = (float*)d_out;

    cudaFuncSetAttribute(lstm_persistent,
                         cudaFuncAttributeMaxDynamicSharedMemorySize, (int)SMEM_BYTES);

    lstm_init_kernel<<<256, 256>>>();
    lstm_persistent<<<GB * GCOL, NTHR, SMEM_BYTES>>>(
        x, Wih1, Whh1, bih1, bhh1, Wih2, Whh2, bih2, bhh2);
    classifier_kernel<<<B_, DMLP_>>>(W1, b1, W2, b2, out);
}